// round 17
// baseline (speedup 1.0000x reference)
#include <cuda_runtime.h>
#include <cuda_fp16.h>
#include <cstdint>

#define N_NODES 4096
#define EMB 10
#define NBATCH 64
#define CI 64
#define CO 64

// ---------------- device scratch (allocation-free rule) --------------------
__device__ __half g_Ah[(size_t)N_NODES * N_NODES];    // softmax(relu(EE^T)) fp16
__device__ __half g_Xh[(size_t)N_NODES * N_NODES];    // X^T[j=b*64+c][m] fp16
__device__ __half g_xh16[(size_t)NBATCH * N_NODES * CI]; // x fp16 [b][n][i]
__device__ __half g_y1h[(size_t)NBATCH * N_NODES * CI];  // y1 fp16 [b][n][c]
__device__ float  g_Wpp[(size_t)EMB * 8192];          // permuted pool [d][o*128+k*64+i]
__device__ __half g_Wt[(size_t)N_NODES * 8192];       // per-node W^T fp16 [n][o][ki]
__device__ int    g_rowdone[32];                      // mma row-block completion (32 j-tiles)
__device__ int    g_wdone[128];                       // Wt 32-node-group completion (4 p-blocks)

// ---------------- PTX helpers ---------------------------------------------
__device__ __forceinline__ uint32_t smem_u32(const void* p) {
    uint32_t a;
    asm("{ .reg .u64 t; cvta.to.shared.u64 t, %1; cvt.u32.u64 %0, t; }" : "=r"(a) : "l"(p));
    return a;
}
__device__ __forceinline__ void cp_async16(uint32_t dst, const void* src) {
    asm volatile("cp.async.cg.shared.global [%0], [%1], 16;" :: "r"(dst), "l"(src));
}
#define CP_COMMIT()  asm volatile("cp.async.commit_group;" ::: "memory")
#define CP_WAIT(N)   asm volatile("cp.async.wait_group %0;" :: "n"(N) : "memory")

__device__ __forceinline__ void ldsm4(uint32_t* r, uint32_t addr) {
    asm volatile("ldmatrix.sync.aligned.m8n8.x4.shared.b16 {%0,%1,%2,%3}, [%4];"
        : "=r"(r[0]), "=r"(r[1]), "=r"(r[2]), "=r"(r[3]) : "r"(addr));
}
__device__ __forceinline__ void mma_f16(float* c, const uint32_t* a,
                                        uint32_t b0, uint32_t b1) {
    asm volatile("mma.sync.aligned.m16n8k16.row.col.f32.f16.f16.f32 "
        "{%0,%1,%2,%3}, {%4,%5,%6,%7}, {%8,%9}, {%0,%1,%2,%3};"
        : "+f"(c[0]), "+f"(c[1]), "+f"(c[2]), "+f"(c[3])
        : "r"(a[0]), "r"(a[1]), "r"(a[2]), "r"(a[3]), "r"(b0), "r"(b1));
}
__device__ __forceinline__ uint32_t h2_bits(float lo, float hi) {
    __half2 h = __floats2half2_rn(lo, hi);
    uint32_t u;
    memcpy(&u, &h, 4);
    return u;
}

// ---------------------------------------------------------------------------
// Kernel A (k_prep): fused transpose / softmax / perm / counter-zero.
// ---------------------------------------------------------------------------
#define SM_ROWS 4
#define PREP_TRANS 4096
#define PREP_SMAX  (PREP_TRANS + N_NODES / SM_ROWS)     // 5120
#define PREP_PERM  (PREP_SMAX + (EMB * 8192) / 256)     // 5440
#define PREP_GRID  (PREP_PERM + 1)

__global__ __launch_bounds__(256) void k_prep(const float* __restrict__ x,
                                              const float* __restrict__ E,
                                              const float* __restrict__ Wp) {
    __shared__ __align__(16) char sbuf[64 * 65 * 4];
    const int bidx = blockIdx.x;
    const int tid = threadIdx.x;

    if (bidx < PREP_TRANS) {
        float (*tile)[65] = (float(*)[65])sbuf;
        const int b = bidx >> 6;
        const int m0 = (bidx & 63) * 64;
#pragma unroll
        for (int i = 0; i < 8; i++) {
            const int idx = tid + i * 256;
            const int mi = idx >> 5;
            const int cp = (idx & 31) * 2;
            const float2 v = *(const float2*)&x[((size_t)b * N_NODES + m0 + mi) * CI + cp];
            tile[mi][cp] = v.x;
            tile[mi][cp + 1] = v.y;
            *(uint32_t*)&g_xh16[((size_t)b * N_NODES + m0 + mi) * CI + cp] = h2_bits(v.x, v.y);
        }
        __syncthreads();
#pragma unroll
        for (int i = 0; i < 8; i++) {
            const int idx = tid + i * 256;
            const int c = idx >> 5;
            const int pm = (idx & 31) * 2;
            *(uint32_t*)&g_Xh[(size_t)(b * 64 + c) * N_NODES + m0 + pm] =
                h2_bits(tile[pm][c], tile[pm + 1][c]);
        }
    } else if (bidx < PREP_SMAX) {
        float* sER = (float*)sbuf;
        float* sred = sER + SM_ROWS * EMB;
        float* sinv = sred + 8 * SM_ROWS;
        const int r0 = (bidx - PREP_TRANS) * SM_ROWS;

        if (tid < SM_ROWS * EMB) sER[tid] = E[r0 * EMB + tid];
        __syncthreads();

        float er[SM_ROWS][EMB];
#pragma unroll
        for (int r = 0; r < SM_ROWS; r++)
#pragma unroll
            for (int d = 0; d < EMB; d++) er[r][d] = sER[r * EMB + d];

        float ssum[SM_ROWS];
#pragma unroll
        for (int r = 0; r < SM_ROWS; r++) ssum[r] = 0.f;

        for (int it = 0; it < 16; it++) {
            const int m = tid + it * 256;
            float em[EMB];
#pragma unroll
            for (int d = 0; d < EMB; d++) em[d] = __ldg(E + m * EMB + d);
#pragma unroll
            for (int r = 0; r < SM_ROWS; r++) {
                float dot = 0.f;
#pragma unroll
                for (int d = 0; d < EMB; d++) dot = fmaf(em[d], er[r][d], dot);
                ssum[r] += __expf(fmaxf(dot, 0.f));
            }
        }
#pragma unroll
        for (int r = 0; r < SM_ROWS; r++)
#pragma unroll
            for (int o = 16; o; o >>= 1) ssum[r] += __shfl_xor_sync(0xffffffffu, ssum[r], o);
        if ((tid & 31) == 0) {
#pragma unroll
            for (int r = 0; r < SM_ROWS; r++) sred[(tid >> 5) * SM_ROWS + r] = ssum[r];
        }
        __syncthreads();
        if (tid < SM_ROWS) {
            float s = 0.f;
#pragma unroll
            for (int w = 0; w < 8; w++) s += sred[w * SM_ROWS + tid];
            sinv[tid] = 1.0f / s;
        }
        __syncthreads();
        float inv[SM_ROWS];
#pragma unroll
        for (int r = 0; r < SM_ROWS; r++) inv[r] = sinv[r];

        for (int it = 0; it < 16; it++) {
            const int m = tid + it * 256;
            float em[EMB];
#pragma unroll
            for (int d = 0; d < EMB; d++) em[d] = __ldg(E + m * EMB + d);
#pragma unroll
            for (int r = 0; r < SM_ROWS; r++) {
                float dot = 0.f;
#pragma unroll
                for (int d = 0; d < EMB; d++) dot = fmaf(em[d], er[r][d], dot);
                g_Ah[(size_t)(r0 + r) * N_NODES + m] =
                    __float2half(__expf(fmaxf(dot, 0.f)) * inv[r]);
            }
        }
    } else if (bidx < PREP_PERM) {
        const int idx = (bidx - PREP_SMAX) * 256 + tid;
        const int d = idx >> 13;
        const int r = idx & 8191;
        const int o = r >> 7;
        const int k = (r >> 6) & 1;
        const int i = r & 63;
        g_Wpp[idx] = Wp[d * 8192 + k * 4096 + i * 64 + o];
    } else {
        if (tid < 32) g_rowdone[tid] = 0;
        else if (tid < 160) g_wdone[tid - 32] = 0;
    }
}

// ---------------------------------------------------------------------------
// Kernel B (k_main), 512-thread blocks, grid 3584:
//   [0, 1024)    : mma tile 128x128, 16 warps (4Mx4N), warp 32x32, KC=64, 3-stage
//   [1024, 1536) : Wt gen (n-group 32 x p-block 2048)
//   [1536, 3584) : out GEMM, 2 nodes/CTA (8 warps each) -> 4096 nodes
// ---------------------------------------------------------------------------
#define KC 64
#define ROWB 144
#define TILE_B (128 * ROWB)
#define STAGE_B (2 * TILE_B)
#define SMEM_MMA (3 * STAGE_B)        // 110592 B
#define NT (N_NODES / KC)
#define KO_PITCH 272
#define KO_TILE (64 * KO_PITCH)        // 17408 B
#define KO_NODE (2 * KO_TILE)          // 34816 B

__global__ __launch_bounds__(512, 2) void k_main(const float* __restrict__ E,
                                                 const float* __restrict__ bp,
                                                 float* __restrict__ out) {
    extern __shared__ __align__(128) char smem[];
    const int tid = threadIdx.x;

    if (blockIdx.x >= 1536) {
        // =================== out GEMM (consumer): 2 nodes, 8 warps each ====
        const int ci = blockIdx.x - 1536;          // 0..2047
        const int nbase = ci * 2;                  // 0..4094
        const int h = tid >> 8;
        const int tl = tid & 255;
        const int n = nbase + h;
        const int wid8 = tl >> 5;
        const int lane = tl & 31;
        const int wm2 = wid8 >> 1;
        const int wn2 = wid8 & 1;

        if (tid == 0) {
            volatile int* rd = g_rowdone;
            volatile int* wd = g_wdone;
            while (rd[nbase >> 7] < 32) __nanosleep(200);
            while (wd[nbase >> 5] < 4) __nanosleep(200);
        }
        __syncthreads();
        __threadfence();

        char* sA = smem + h * KO_NODE;
        char* sW = smem + h * KO_NODE + KO_TILE;
        float* sbias = (float*)(smem + 2 * KO_NODE) + h * 64;
        float* sE = (float*)(smem + 2 * KO_NODE + 512) + h * 16;
        const uint32_t aA = smem_u32(sA);
        const uint32_t aW = smem_u32(sW);

#pragma unroll
        for (int i = 0; i < 4; i++) {
            const int s = tl + i * 256;
            const int row = s >> 4, seg = s & 15;
            cp_async16(aW + row * KO_PITCH + seg * 16,
                       g_Wt + (size_t)n * 8192 + row * 128 + seg * 8);
        }
#pragma unroll
        for (int i = 0; i < 2; i++) {
            const int s = tl + i * 256;
            const int b = s >> 3, seg = s & 7;
            cp_async16(aA + b * KO_PITCH + seg * 16,
                       g_xh16 + ((size_t)b * N_NODES + n) * CI + seg * 8);
            cp_async16(aA + b * KO_PITCH + 128 + seg * 16,
                       g_y1h + ((size_t)b * N_NODES + n) * CI + seg * 8);
        }
        CP_COMMIT();

        if (tl < EMB) sE[tl] = E[n * EMB + tl];
        __syncthreads();
        if (tl < 64) {
            float acc = 0.f;
#pragma unroll
            for (int d = 0; d < EMB; d++) acc = fmaf(sE[d], bp[d * 64 + tl], acc);
            sbias[tl] = acc;
        }
        CP_WAIT(0);
        __syncthreads();

        const uint32_t offA = (uint32_t)((wm2 * 16 + (lane & 15)) * KO_PITCH + (lane >> 4) * 16);
        uint32_t offB[2];
#pragma unroll
        for (int nb = 0; nb < 2; nb++)
            offB[nb] = (uint32_t)((wn2 * 32 + nb * 16 + (lane & 15)) * KO_PITCH + (lane >> 4) * 16);

        float acc[4][4];
#pragma unroll
        for (int q = 0; q < 4; q++)
#pragma unroll
            for (int r = 0; r < 4; r++) acc[q][r] = 0.f;

#pragma unroll
        for (int ks = 0; ks < 8; ks++) {
            const uint32_t ko = ks * 32;
            uint32_t ah[4];
            ldsm4(ah, aA + offA + ko);
#pragma unroll
            for (int nb = 0; nb < 2; nb++) {
                uint32_t bh[4];
                ldsm4(bh, aW + offB[nb] + ko);
                mma_f16(acc[nb * 2 + 0], ah, bh[0], bh[2]);
                mma_f16(acc[nb * 2 + 1], ah, bh[1], bh[3]);
            }
        }

        const int brow = wm2 * 16 + (lane >> 2);
#pragma unroll
        for (int q = 0; q < 4; q++) {
            const int o = wn2 * 32 + q * 8 + (lane & 3) * 2;
            const float2 bias = *(const float2*)&sbias[o];
            float2 v0 = {acc[q][0] + bias.x, acc[q][1] + bias.y};
            float2 v1 = {acc[q][2] + bias.x, acc[q][3] + bias.y};
            *(float2*)&out[((size_t)brow * N_NODES + n) * CO + o] = v0;
            *(float2*)&out[((size_t)(brow + 8) * N_NODES + n) * CO + o] = v1;
        }
        return;
    }

    if (blockIdx.x >= 1024) {
        // =================== wgen (producer): 512 blocks ===================
        const int wb = blockIdx.x - 1024;
        const int n0 = (wb >> 2) * 32;
        const int p0 = (wb & 3) * 2048;
        float* sE = (float*)smem;      // [32*EMB]

        for (int s = tid; s < 32 * EMB; s += 512)
            sE[s] = E[n0 * EMB + s];

        const int p = p0 + tid * 4;
        float4 w[EMB];
#pragma unroll
        for (int d = 0; d < EMB; d++) w[d] = *(const float4*)&g_Wpp[(size_t)d * 8192 + p];
        __syncthreads();

#pragma unroll 4
        for (int nn = 0; nn < 32; nn++) {
            float4 acc = {0.f, 0.f, 0.f, 0.f};
#pragma unroll
            for (int d = 0; d < EMB; d++) {
                const float e = sE[nn * EMB + d];
                acc.x = fmaf(e, w[d].x, acc.x);
                acc.y = fmaf(e, w[d].y, acc.y);
                acc.z = fmaf(e, w[d].z, acc.z);
                acc.w = fmaf(e, w[d].w, acc.w);
            }
            uint2 pk;
            pk.x = h2_bits(acc.x, acc.y);
            pk.y = h2_bits(acc.z, acc.w);
            *(uint2*)&g_Wt[(size_t)(n0 + nn) * 8192 + p] = pk;
        }
        __threadfence();
        __syncthreads();
        if (tid == 0) atomicAdd(&g_wdone[wb >> 2], 1);
        return;
    }

    // =================== diffusion mma tile: 16 warps, warp 32x32 ==========
    const uint32_t sb = smem_u32(smem);
    const int wid = tid >> 5;
    const int lane = tid & 31;
    const int wm = wid >> 2;
    const int wn = wid & 3;
    const int n0 = (blockIdx.x >> 5) * 128;
    const int j0 = (blockIdx.x & 31) * 128;

    int grow[2], gseg[2];
    uint32_t sdst[2];
#pragma unroll
    for (int i = 0; i < 2; i++) {
        const int s = tid + i * 512;
        grow[i] = s >> 3;
        gseg[i] = s & 7;
        sdst[i] = (uint32_t)(grow[i] * ROWB + gseg[i] * 16);
    }

    uint32_t offA[2], offB[2];
#pragma unroll
    for (int mb = 0; mb < 2; mb++)
        offA[mb] = (uint32_t)((wm * 32 + mb * 16 + (lane & 15)) * ROWB + (lane >> 4) * 16);
#pragma unroll
    for (int nb = 0; nb < 2; nb++)
        offB[nb] = (uint32_t)((wn * 32 + nb * 16 + (lane & 15)) * ROWB + (lane >> 4) * 16);

    float acc[2][4][4];
#pragma unroll
    for (int mb = 0; mb < 2; mb++)
#pragma unroll
        for (int q = 0; q < 4; q++)
#pragma unroll
            for (int r = 0; r < 4; r++) acc[mb][q][r] = 0.f;

#pragma unroll
    for (int c = 0; c < 2; c++) {
        const uint32_t st = sb + c * STAGE_B;
        const int m0 = c * KC;
#pragma unroll
        for (int i = 0; i < 2; i++) {
            cp_async16(st + sdst[i],          g_Ah + (size_t)(n0 + grow[i]) * N_NODES + m0 + gseg[i] * 8);
            cp_async16(st + TILE_B + sdst[i], g_Xh + (size_t)(j0 + grow[i]) * N_NODES + m0 + gseg[i] * 8);
        }
        CP_COMMIT();
    }

    int scur = 0, sld = 2;
    for (int t = 0; t < NT; t++) {
        if (t < NT - 1) { CP_WAIT(1); } else { CP_WAIT(0); }
        __syncthreads();

        if (t + 2 < NT) {
            const uint32_t st = sb + sld * STAGE_B;
            const int m0 = (t + 2) * KC;
#pragma unroll
            for (int i = 0; i < 2; i++) {
                cp_async16(st + sdst[i],          g_Ah + (size_t)(n0 + grow[i]) * N_NODES + m0 + gseg[i] * 8);
                cp_async16(st + TILE_B + sdst[i], g_Xh + (size_t)(j0 + grow[i]) * N_NODES + m0 + gseg[i] * 8);
            }
            CP_COMMIT();
        }

        const uint32_t bA = sb + scur * STAGE_B;
        const uint32_t bB = bA + TILE_B;
#pragma unroll
        for (int ks = 0; ks < 4; ks++) {
            const uint32_t ko = ks * 32;
            uint32_t ah[2][4];
#pragma unroll
            for (int mb = 0; mb < 2; mb++) ldsm4(ah[mb], bA + offA[mb] + ko);
#pragma unroll
            for (int nb = 0; nb < 2; nb++) {
                uint32_t bh[4];
                ldsm4(bh, bB + offB[nb] + ko);
#pragma unroll
                for (int mb = 0; mb < 2; mb++) {
                    mma_f16(acc[mb][nb * 2 + 0], ah[mb], bh[0], bh[2]);
                    mma_f16(acc[mb][nb * 2 + 1], ah[mb], bh[1], bh[3]);
                }
            }
        }
        scur = (scur == 2) ? 0 : scur + 1;
        sld = (sld == 2) ? 0 : sld + 1;
    }

    const int b = (j0 + wn * 32) >> 6;
#pragma unroll
    for (int mb = 0; mb < 2; mb++) {
        const int nrow = n0 + wm * 32 + mb * 16 + (lane >> 2);
#pragma unroll
        for (int q = 0; q < 4; q++) {
            const int c = ((wn * 32 + q * 8) & 63) + (lane & 3) * 2;
            const uint32_t v0 = h2_bits(acc[mb][q][0], acc[mb][q][1]);
            const uint32_t v1 = h2_bits(acc[mb][q][2], acc[mb][q][3]);
            *(uint32_t*)&g_y1h[((size_t)b * N_NODES + nrow) * CI + c] = v0;
            *(uint32_t*)&g_y1h[((size_t)b * N_NODES + nrow + 8) * CI + c] = v1;
        }
    }
    __threadfence();
    __syncthreads();
    if (tid == 0) atomicAdd(&g_rowdone[blockIdx.x >> 5], 1);
}

// ---------------------------------------------------------------------------
extern "C" void kernel_launch(void* const* d_in, const int* in_sizes, int n_in,
                              void* d_out, int out_size) {
    const float* x  = (const float*)d_in[0];
    const float* E  = (const float*)d_in[1];
    const float* Wp = (const float*)d_in[2];
    const float* bp = (const float*)d_in[3];
    float* out = (float*)d_out;

    cudaFuncSetAttribute(k_main, cudaFuncAttributeMaxDynamicSharedMemorySize, SMEM_MMA);

    k_prep<<<PREP_GRID, 256>>>(x, E, Wp);
    k_main<<<3584, 512, SMEM_MMA>>>(E, bp, out);
}